// round 1
// baseline (speedup 1.0000x reference)
#include <cuda_runtime.h>

#define S_LEN   2048
#define D_MODEL 2048
#define NH      32
#define NBITS   8
#define HB      256   // NH * NBITS

// ---------------- scratch (device globals: no allocation allowed) ----------
__device__ float g_pq[S_LEN * HB];
__device__ float g_pk[S_LEN * HB];
__device__ float g_pv[S_LEN * HB];
__device__ float g_ao[S_LEN * HB];        // interpolated attention output [S, HB]
__device__ float g_O [S_LEN * D_MODEL];   // attention @ Wo

__device__ __forceinline__ float sigmoidf_(float x) {
    return 1.0f / (1.0f + __expf(-x));
}

// ---------------------------------------------------------------------------
// Fused QKV projection: P = sigmoid(hs @ W{q,k,v}), tiles 64x64, BK=16.
// grid (12, 32): blockIdx.x selects 64-wide n-tile of the virtual [2048,768] GEMM.
// ---------------------------------------------------------------------------
__global__ __launch_bounds__(256) void qkv_gemm(
    const float* __restrict__ A,
    const float* __restrict__ Wq,
    const float* __restrict__ Wk,
    const float* __restrict__ Wv)
{
    __shared__ float As[16][64];
    __shared__ float Bs[16][64];

    const int tid = threadIdx.x;
    const int n0g = blockIdx.x * 64;     // 0..704
    const int m0  = blockIdx.y * 64;

    const float* Bp;
    float*       Cp;
    int ncol0;
    if (n0g < 256)      { Bp = Wq; Cp = g_pq; ncol0 = n0g; }
    else if (n0g < 512) { Bp = Wk; Cp = g_pk; ncol0 = n0g - 256; }
    else                { Bp = Wv; Cp = g_pv; ncol0 = n0g - 512; }

    const int aRow = tid >> 2, aCol = (tid & 3) * 4;
    const int bRow = tid >> 4, bCol = (tid & 15) * 4;
    const int tx = tid & 15, ty = tid >> 4;

    float acc[4][4] = {};

    for (int k0 = 0; k0 < D_MODEL; k0 += 16) {
        float4 av = *(const float4*)&A[(m0 + aRow) * D_MODEL + k0 + aCol];
        As[aCol + 0][aRow] = av.x;
        As[aCol + 1][aRow] = av.y;
        As[aCol + 2][aRow] = av.z;
        As[aCol + 3][aRow] = av.w;
        *(float4*)&Bs[bRow][bCol] =
            *(const float4*)&Bp[(k0 + bRow) * HB + ncol0 + bCol];
        __syncthreads();

        #pragma unroll
        for (int kk = 0; kk < 16; kk++) {
            float4 a4 = *(const float4*)&As[kk][ty * 4];
            float4 b4 = *(const float4*)&Bs[kk][tx * 4];
            float a[4] = {a4.x, a4.y, a4.z, a4.w};
            float b[4] = {b4.x, b4.y, b4.z, b4.w};
            #pragma unroll
            for (int i = 0; i < 4; i++)
                #pragma unroll
                for (int j = 0; j < 4; j++)
                    acc[i][j] = fmaf(a[i], b[j], acc[i][j]);
        }
        __syncthreads();
    }

    #pragma unroll
    for (int i = 0; i < 4; i++) {
        float4 o;
        o.x = sigmoidf_(acc[i][0]);
        o.y = sigmoidf_(acc[i][1]);
        o.z = sigmoidf_(acc[i][2]);
        o.w = sigmoidf_(acc[i][3]);
        *(float4*)&Cp[(m0 + ty * 4 + i) * HB + ncol0 + tx * 4] = o;
    }
}

// ---------------------------------------------------------------------------
// Causal ROSA attention.  scores in [0,8] -> fixed softmax reference 8,
// no running max needed.  2 queries per thread (BQ=256, 128 threads).
// grid (8, 32) = (qblock, head).
// ---------------------------------------------------------------------------
__global__ __launch_bounds__(128) void attn_kernel(
    const float* __restrict__ e0, const float* __restrict__ e1)
{
    __shared__ float sk[128][8];
    __shared__ float sv[128][8];
    __shared__ float ssum[128];

    const int tid = threadIdx.x;
    const int h   = blockIdx.y;
    const int qb  = blockIdx.x;
    const int q0  = qb * 256 + tid;
    const int q1  = q0 + 128;
    const int c0  = h * NBITS;

    float qr0[8], qr1[8];
    {
        const float* p0 = &g_pq[q0 * HB + c0];
        const float* p1 = &g_pq[q1 * HB + c0];
        *(float4*)&qr0[0] = *(const float4*)(p0);
        *(float4*)&qr0[4] = *(const float4*)(p0 + 4);
        *(float4*)&qr1[0] = *(const float4*)(p1);
        *(float4*)&qr1[4] = *(const float4*)(p1 + 4);
    }
    float sq0 = 0.f, sq1 = 0.f;
    #pragma unroll
    for (int d = 0; d < 8; d++) { sq0 += qr0[d]; sq1 += qr1[d]; }

    float l0 = 0.f, l1 = 0.f;
    float acc0[8] = {}, acc1[8] = {};

    const int ntiles = (qb + 1) * 2;
    for (int kb = 0; kb < ntiles; kb++) {
        // cooperative load of K/V tile (128 rows)
        {
            const int krow = kb * 128 + tid;
            const float* pk = &g_pk[krow * HB + c0];
            const float* pv = &g_pv[krow * HB + c0];
            float4 k0v = *(const float4*)(pk);
            float4 k1v = *(const float4*)(pk + 4);
            *(float4*)&sk[tid][0] = k0v;
            *(float4*)&sk[tid][4] = k1v;
            ssum[tid] = k0v.x + k0v.y + k0v.z + k0v.w +
                        k1v.x + k1v.y + k1v.z + k1v.w;
            *(float4*)&sv[tid][0] = *(const float4*)(pv);
            *(float4*)&sv[tid][4] = *(const float4*)(pv + 4);
        }
        __syncthreads();

        const int lim0 = q0 - kb * 128;            // causal limit (inclusive)
        const int lim1 = q1 - kb * 128;
        const int jend = min(128, lim1 + 1);

        for (int j = 0; j < jend; j++) {
            float4 ka = *(const float4*)&sk[j][0];
            float4 kb4 = *(const float4*)&sk[j][4];
            float d0 = qr0[0] * ka.x;
            d0 = fmaf(qr0[1], ka.y, d0);  d0 = fmaf(qr0[2], ka.z, d0);
            d0 = fmaf(qr0[3], ka.w, d0);  d0 = fmaf(qr0[4], kb4.x, d0);
            d0 = fmaf(qr0[5], kb4.y, d0); d0 = fmaf(qr0[6], kb4.z, d0);
            d0 = fmaf(qr0[7], kb4.w, d0);
            float d1 = qr1[0] * ka.x;
            d1 = fmaf(qr1[1], ka.y, d1);  d1 = fmaf(qr1[2], ka.z, d1);
            d1 = fmaf(qr1[3], ka.w, d1);  d1 = fmaf(qr1[4], kb4.x, d1);
            d1 = fmaf(qr1[5], kb4.y, d1); d1 = fmaf(qr1[6], kb4.z, d1);
            d1 = fmaf(qr1[7], kb4.w, d1);
            const float sb = ssum[j];
            // exp(score - 8) = exp(2*dot - sq - sk)  (score <= 8 always)
            float p0 = __expf(2.f * d0 - sq0 - sb);
            float p1 = __expf(2.f * d1 - sq1 - sb);
            if (j > lim0) p0 = 0.f;
            l0 += p0; l1 += p1;
            float4 va = *(const float4*)&sv[j][0];
            float4 vb = *(const float4*)&sv[j][4];
            acc0[0] = fmaf(p0, va.x, acc0[0]); acc0[1] = fmaf(p0, va.y, acc0[1]);
            acc0[2] = fmaf(p0, va.z, acc0[2]); acc0[3] = fmaf(p0, va.w, acc0[3]);
            acc0[4] = fmaf(p0, vb.x, acc0[4]); acc0[5] = fmaf(p0, vb.y, acc0[5]);
            acc0[6] = fmaf(p0, vb.z, acc0[6]); acc0[7] = fmaf(p0, vb.w, acc0[7]);
            acc1[0] = fmaf(p1, va.x, acc1[0]); acc1[1] = fmaf(p1, va.y, acc1[1]);
            acc1[2] = fmaf(p1, va.z, acc1[2]); acc1[3] = fmaf(p1, va.w, acc1[3]);
            acc1[4] = fmaf(p1, vb.x, acc1[4]); acc1[5] = fmaf(p1, vb.y, acc1[5]);
            acc1[6] = fmaf(p1, vb.z, acc1[6]); acc1[7] = fmaf(p1, vb.w, acc1[7]);
        }
        __syncthreads();
    }

    const float inv0 = 1.f / l0;
    const float inv1 = 1.f / l1;
    #pragma unroll
    for (int d = 0; d < 8; d++) {
        const float a  = e0[c0 + d];
        const float bd = e1[c0 + d] - a;
        g_ao[q0 * HB + c0 + d] = fmaf(bd, acc0[d] * inv0, a);
        g_ao[q1 * HB + c0 + d] = fmaf(bd, acc1[d] * inv1, a);
    }
}

// ---------------------------------------------------------------------------
// Generic fp32 SGEMM, 128x128 tile, BK=16, 8x8 per thread.
// EPI 0: C = acc            (used for O = g_ao @ Wo)
// EPI 1: C = sigmoid(acc) * Dm   (final gated output)
// ---------------------------------------------------------------------------
template <int EPI>
__global__ __launch_bounds__(256) void sgemm128(
    const float* __restrict__ A, const float* __restrict__ B,
    float* __restrict__ C, int N, int K, const float* __restrict__ Dm)
{
    __shared__ float As[16][128];
    __shared__ float Bs[16][128];

    const int tid = threadIdx.x;
    const int m0 = blockIdx.y * 128, n0 = blockIdx.x * 128;
    const int aRow = tid >> 2, aCol = (tid & 3) * 4;
    const int bRow = tid >> 5, bCol = (tid & 31) * 4;
    const int tx = tid & 15, ty = tid >> 4;

    float acc[8][8] = {};

    for (int k0 = 0; k0 < K; k0 += 16) {
        float4 av0 = *(const float4*)&A[(m0 + aRow) * K + k0 + aCol];
        float4 av1 = *(const float4*)&A[(m0 + aRow + 64) * K + k0 + aCol];
        As[aCol + 0][aRow] = av0.x; As[aCol + 1][aRow] = av0.y;
        As[aCol + 2][aRow] = av0.z; As[aCol + 3][aRow] = av0.w;
        As[aCol + 0][aRow + 64] = av1.x; As[aCol + 1][aRow + 64] = av1.y;
        As[aCol + 2][aRow + 64] = av1.z; As[aCol + 3][aRow + 64] = av1.w;
        *(float4*)&Bs[bRow][bCol] =
            *(const float4*)&B[(k0 + bRow) * N + n0 + bCol];
        *(float4*)&Bs[bRow + 8][bCol] =
            *(const float4*)&B[(k0 + bRow + 8) * N + n0 + bCol];
        __syncthreads();

        #pragma unroll
        for (int kk = 0; kk < 16; kk++) {
            float a[8], b[8];
            *(float4*)&a[0] = *(const float4*)&As[kk][ty * 8];
            *(float4*)&a[4] = *(const float4*)&As[kk][ty * 8 + 4];
            *(float4*)&b[0] = *(const float4*)&Bs[kk][tx * 8];
            *(float4*)&b[4] = *(const float4*)&Bs[kk][tx * 8 + 4];
            #pragma unroll
            for (int i = 0; i < 8; i++)
                #pragma unroll
                for (int j = 0; j < 8; j++)
                    acc[i][j] = fmaf(a[i], b[j], acc[i][j]);
        }
        __syncthreads();
    }

    #pragma unroll
    for (int i = 0; i < 8; i++) {
        const int row = m0 + ty * 8 + i;
        #pragma unroll
        for (int j4 = 0; j4 < 2; j4++) {
            const int col = n0 + tx * 8 + j4 * 4;
            float4 o;
            if (EPI == 0) {
                o.x = acc[i][j4 * 4 + 0]; o.y = acc[i][j4 * 4 + 1];
                o.z = acc[i][j4 * 4 + 2]; o.w = acc[i][j4 * 4 + 3];
            } else {
                float4 dv = *(const float4*)&Dm[row * N + col];
                o.x = sigmoidf_(acc[i][j4 * 4 + 0]) * dv.x;
                o.y = sigmoidf_(acc[i][j4 * 4 + 1]) * dv.y;
                o.z = sigmoidf_(acc[i][j4 * 4 + 2]) * dv.z;
                o.w = sigmoidf_(acc[i][j4 * 4 + 3]) * dv.w;
            }
            *(float4*)&C[row * N + col] = o;
        }
    }
}

// ---------------------------------------------------------------------------
extern "C" void kernel_launch(void* const* d_in, const int* in_sizes, int n_in,
                              void* d_out, int out_size)
{
    const float* hs = (const float*)d_in[0];
    const float* Wq = (const float*)d_in[1];
    const float* Wk = (const float*)d_in[2];
    const float* Wv = (const float*)d_in[3];
    const float* Wo = (const float*)d_in[4];
    const float* Wg = (const float*)d_in[5];
    const float* e0 = (const float*)d_in[6];
    const float* e1 = (const float*)d_in[7];
    float* out = (float*)d_out;

    float *pao, *pO;
    cudaGetSymbolAddress((void**)&pao, g_ao);
    cudaGetSymbolAddress((void**)&pO,  g_O);

    // 1) pq/pk/pv = sigmoid(hs @ W{q,k,v})
    qkv_gemm<<<dim3(12, 32), 256>>>(hs, Wq, Wk, Wv);
    // 2) causal ROSA attention + value-embedding interpolation -> g_ao
    attn_kernel<<<dim3(8, NH), 128>>>(e0, e1);
    // 3) O = g_ao @ Wo
    sgemm128<0><<<dim3(16, 16), 256>>>(pao, Wo, pO, D_MODEL, HB, nullptr);
    // 4) out = sigmoid(hs @ Wg) * O   (fused final epilogue)
    sgemm128<1><<<dim3(16, 16), 256>>>(hs, Wg, out, D_MODEL, D_MODEL, pO);
}

// round 3
// speedup vs baseline: 3.1011x; 3.1011x over previous
#include <cuda_runtime.h>
#include <cuda_bf16.h>
#include <cstdint>

#define S_LEN   2048
#define D_MODEL 2048
#define NH      32
#define NBITS   8
#define HB      256   // NH * NBITS

// ---------------- scratch (device globals: no allocation allowed) ----------
__device__ float g_pq[S_LEN * HB];
__device__ float g_pk[S_LEN * HB];
__device__ float g_pv[S_LEN * HB];
__device__ float g_ao[S_LEN * HB];        // interpolated attention output [S, HB]
__device__ float g_O [S_LEN * D_MODEL];   // attention @ Wo

// bf16 split operands
__device__ __nv_bfloat16 g_ahi[S_LEN * D_MODEL];     // hs hi
__device__ __nv_bfloat16 g_alo[S_LEN * D_MODEL];     // hs lo
__device__ __nv_bfloat16 g_bg_hi[D_MODEL * D_MODEL]; // Wg^T
__device__ __nv_bfloat16 g_bg_lo[D_MODEL * D_MODEL];
__device__ __nv_bfloat16 g_bqkv_hi[768 * D_MODEL];   // [Wq^T;Wk^T;Wv^T]
__device__ __nv_bfloat16 g_bqkv_lo[768 * D_MODEL];
__device__ __nv_bfloat16 g_bo_hi[D_MODEL * HB];      // Wo^T
__device__ __nv_bfloat16 g_bo_lo[D_MODEL * HB];
__device__ __nv_bfloat16 g_aoh[S_LEN * HB];          // ao hi
__device__ __nv_bfloat16 g_aol[S_LEN * HB];          // ao lo

__device__ __forceinline__ float sigmoidf_(float x) {
    return 1.0f / (1.0f + __expf(-x));
}

__device__ __forceinline__ uint32_t smem_u32(const void* p) {
    uint32_t a;
    asm("{ .reg .u64 t; cvta.to.shared.u64 t, %1; cvt.u32.u64 %0, t; }"
        : "=r"(a) : "l"(p));
    return a;
}

#define CP_ASYNC16(sa, ga) \
    asm volatile("cp.async.cg.shared.global [%0], [%1], 16;" :: "r"(sa), "l"(ga))
#define CP_COMMIT() asm volatile("cp.async.commit_group;" ::: "memory")
#define CP_WAIT1()  asm volatile("cp.async.wait_group 1;" ::: "memory")
#define CP_WAIT0()  asm volatile("cp.async.wait_group 0;" ::: "memory")

#define LDSM4(r0, r1, r2, r3, a) \
    asm volatile("ldmatrix.sync.aligned.m8n8.x4.shared.b16 {%0,%1,%2,%3}, [%4];" \
                 : "=r"(r0), "=r"(r1), "=r"(r2), "=r"(r3) : "r"(a))

#define MMA16816(c, a, b) \
    asm volatile("mma.sync.aligned.m16n8k16.row.col.f32.bf16.bf16.f32 " \
                 "{%0,%1,%2,%3}, {%4,%5,%6,%7}, {%8,%9}, {%0,%1,%2,%3};" \
                 : "+f"((c)[0]), "+f"((c)[1]), "+f"((c)[2]), "+f"((c)[3]) \
                 : "r"((a)[0]), "r"((a)[1]), "r"((a)[2]), "r"((a)[3]), \
                   "r"((b)[0]), "r"((b)[1]))

__device__ __forceinline__ uint32_t sw128(uint32_t off) {
    return off ^ ((off >> 3) & 0x70);
}

// ---------------------------------------------------------------------------
// Conversion kernels: fp32 -> bf16 hi + bf16 lo
// ---------------------------------------------------------------------------
__global__ __launch_bounds__(256) void conv_split(
    const float* __restrict__ x, __nv_bfloat16* __restrict__ hi,
    __nv_bfloat16* __restrict__ lo, int n)
{
    int i = (blockIdx.x * blockDim.x + threadIdx.x) * 4;
    if (i >= n) return;
    float4 v = *(const float4*)(x + i);
    __nv_bfloat16 h0 = __float2bfloat16(v.x), h1 = __float2bfloat16(v.y);
    __nv_bfloat16 h2 = __float2bfloat16(v.z), h3 = __float2bfloat16(v.w);
    *(__nv_bfloat162*)(hi + i)     = __nv_bfloat162(h0, h1);
    *(__nv_bfloat162*)(hi + i + 2) = __nv_bfloat162(h2, h3);
    *(__nv_bfloat162*)(lo + i)     = __nv_bfloat162(
        __float2bfloat16(v.x - __bfloat162float(h0)),
        __float2bfloat16(v.y - __bfloat162float(h1)));
    *(__nv_bfloat162*)(lo + i + 2) = __nv_bfloat162(
        __float2bfloat16(v.z - __bfloat162float(h2)),
        __float2bfloat16(v.w - __bfloat162float(h3)));
}

// W [K x N] fp32 -> out [N x K] bf16 (hi/lo). grid (N/32, K/32), block (32,8)
__global__ void conv_split_T(
    const float* __restrict__ W, __nv_bfloat16* __restrict__ hi,
    __nv_bfloat16* __restrict__ lo, int K, int N)
{
    __shared__ float t[32][33];
    const int n0 = blockIdx.x * 32, k0 = blockIdx.y * 32;
    const int tx = threadIdx.x, ty = threadIdx.y;
    #pragma unroll
    for (int i = 0; i < 4; i++)
        t[ty + 8 * i][tx] = W[(size_t)(k0 + ty + 8 * i) * N + n0 + tx];
    __syncthreads();
    #pragma unroll
    for (int i = 0; i < 4; i++) {
        int r = ty + 8 * i;
        float v = t[tx][r];
        __nv_bfloat16 h = __float2bfloat16(v);
        size_t idx = (size_t)(n0 + r) * K + k0 + tx;
        hi[idx] = h;
        lo[idx] = __float2bfloat16(v - __bfloat162float(h));
    }
}

// ---------------------------------------------------------------------------
// HMMA bf16-split GEMM.  C[M,N] = A[M,K] @ B[N,K]^T, A/B = hi+lo (3 products).
// CTA 128x128, K-chunk 64, cp.async double-buffered, SW128 smem, ldmatrix.
// 8 warps: wm = wid&1 (64 rows), wn = wid>>1 (32 cols). Warp tile 64x32.
// EPI 0: plain fp32 store to C0
// EPI 1: sigmoid -> split pq/pk/pv (C0/C1/C2), each row stride HB
// EPI 2: sigmoid(acc) * Dm -> C0
// ---------------------------------------------------------------------------
#define TILE_B   16384                 // 128 rows x 128 bytes
#define STAGE_B  (4 * TILE_B)          // Ahi, Alo, Bhi, Blo
#define GSMEM    (2 * STAGE_B)         // 131072

template <int EPI>
__global__ __launch_bounds__(256, 1) void mma_gemm(
    const __nv_bfloat16* __restrict__ Ahi, const __nv_bfloat16* __restrict__ Alo,
    const __nv_bfloat16* __restrict__ Bhi, const __nv_bfloat16* __restrict__ Blo,
    int K, float* __restrict__ C0, float* __restrict__ C1, float* __restrict__ C2,
    const float* __restrict__ Dm, int Ntot)
{
    extern __shared__ char smem[];
    const uint32_t sbase = smem_u32(smem);
    const int tid  = threadIdx.x;
    const int wid  = tid >> 5;
    const int lane = tid & 31;
    const int m0 = blockIdx.y * 128;
    const int n0 = blockIdx.x * 128;
    const int wm = (wid & 1) * 64;
    const int wn = (wid >> 1) * 32;

    float acc[4][4][4] = {};
    const int nch = K >> 6;

    // ---- chunk loader: 16 cp.async per thread (4 per tile) ----
    auto load_chunk = [&](int c, int buf) {
        const uint32_t st = sbase + buf * STAGE_B;
        const int k0 = c << 6;
        #pragma unroll
        for (int i = 0; i < 4; i++) {
            const int cc  = tid + (i << 8);
            const int row = cc >> 3;
            const int c16 = cc & 7;
            const uint32_t sw = sw128((uint32_t)(row << 7) | (c16 << 4));
            const size_t ia = (size_t)(m0 + row) * K + k0 + c16 * 8;
            const size_t ib = (size_t)(n0 + row) * K + k0 + c16 * 8;
            CP_ASYNC16(st + sw,              Ahi + ia);
            CP_ASYNC16(st + TILE_B + sw,     Alo + ia);
            CP_ASYNC16(st + 2 * TILE_B + sw, Bhi + ib);
            CP_ASYNC16(st + 3 * TILE_B + sw, Blo + ib);
        }
        CP_COMMIT();
    };

    load_chunk(0, 0);

    for (int c = 0; c < nch; c++) {
        const int cur = c & 1;
        if (c + 1 < nch) load_chunk(c + 1, cur ^ 1);
        if (c + 1 < nch) { CP_WAIT1(); } else { CP_WAIT0(); }
        __syncthreads();

        const uint32_t tb  = sbase + cur * STAGE_B;
        const uint32_t aAh = tb;
        const uint32_t aAl = tb + TILE_B;
        const uint32_t aBh = tb + 2 * TILE_B;
        const uint32_t aBl = tb + 3 * TILE_B;

        #pragma unroll
        for (int s = 0; s < 4; s++) {
            uint32_t ah[4][4], al[4][4], bh[4][2], bl[4][2];
            const uint32_t bcol = (s << 5) | ((lane >> 4) << 4);
            #pragma unroll
            for (int i = 0; i < 4; i++) {
                const int row = wm + i * 16 + (lane & 15);
                const uint32_t sw = sw128((uint32_t)(row << 7) | bcol);
                LDSM4(ah[i][0], ah[i][1], ah[i][2], ah[i][3], aAh + sw);
                LDSM4(al[i][0], al[i][1], al[i][2], al[i][3], aAl + sw);
            }
            #pragma unroll
            for (int j2 = 0; j2 < 2; j2++) {
                const int row = wn + j2 * 16 + (lane & 15);
                const uint32_t sw = sw128((uint32_t)(row << 7) | bcol);
                uint32_t r0, r1, r2, r3;
                LDSM4(r0, r1, r2, r3, aBh + sw);
                bh[j2 * 2][0] = r0; bh[j2 * 2 + 1][0] = r1;
                bh[j2 * 2][1] = r2; bh[j2 * 2 + 1][1] = r3;
                LDSM4(r0, r1, r2, r3, aBl + sw);
                bl[j2 * 2][0] = r0; bl[j2 * 2 + 1][0] = r1;
                bl[j2 * 2][1] = r2; bl[j2 * 2 + 1][1] = r3;
            }
            #pragma unroll
            for (int i = 0; i < 4; i++)
                #pragma unroll
                for (int j = 0; j < 4; j++) {
                    MMA16816(acc[i][j], ah[i], bh[j]);
                    MMA16816(acc[i][j], ah[i], bl[j]);
                    MMA16816(acc[i][j], al[i], bh[j]);
                }
        }
        __syncthreads();
    }

    // ---- epilogue: each thread owns 2 cols x 2 rows per (i,j) tile ----
    #pragma unroll
    for (int i = 0; i < 4; i++) {
        #pragma unroll
        for (int j = 0; j < 4; j++) {
            const int colg = n0 + wn + j * 8 + (lane & 3) * 2;
            #pragma unroll
            for (int h = 0; h < 2; h++) {
                const int rowg = m0 + wm + i * 16 + (lane >> 2) + h * 8;
                float v0 = acc[i][j][h * 2 + 0];
                float v1 = acc[i][j][h * 2 + 1];
                if (EPI == 0) {
                    *(float2*)&C0[(size_t)rowg * Ntot + colg] = make_float2(v0, v1);
                } else if (EPI == 1) {
                    float* dst = (colg < 256) ? C0 : (colg < 512 ? C1 : C2);
                    *(float2*)&dst[(size_t)rowg * HB + (colg & 255)] =
                        make_float2(sigmoidf_(v0), sigmoidf_(v1));
                } else {
                    const float2 dv = *(const float2*)&Dm[(size_t)rowg * Ntot + colg];
                    *(float2*)&C0[(size_t)rowg * Ntot + colg] =
                        make_float2(sigmoidf_(v0) * dv.x, sigmoidf_(v1) * dv.y);
                }
            }
        }
    }
}

// ---------------------------------------------------------------------------
// Causal ROSA attention. 1 query/thread, BQ=128, grid (16, 32).
// scores in [0,8] -> fixed softmax reference, no running max.
// ---------------------------------------------------------------------------
__global__ __launch_bounds__(128) void attn_kernel(
    const float* __restrict__ e0, const float* __restrict__ e1)
{
    __shared__ float sk[128][8];
    __shared__ float sv[128][8];
    __shared__ float ssum[128];

    const int tid = threadIdx.x;
    const int h   = blockIdx.y;
    const int qb  = blockIdx.x;
    const int q0  = qb * 128 + tid;
    const int c0  = h * NBITS;

    float qr[8];
    {
        const float* p0 = &g_pq[(size_t)q0 * HB + c0];
        *(float4*)&qr[0] = *(const float4*)(p0);
        *(float4*)&qr[4] = *(const float4*)(p0 + 4);
    }
    float sq = 0.f;
    #pragma unroll
    for (int d = 0; d < 8; d++) sq += qr[d];

    float l = 0.f;
    float acc[8] = {};

    const int ntiles = qb + 1;
    for (int kb = 0; kb < ntiles; kb++) {
        {
            const int krow = kb * 128 + tid;
            const float* pk = &g_pk[(size_t)krow * HB + c0];
            const float* pv = &g_pv[(size_t)krow * HB + c0];
            float4 k0v = *(const float4*)(pk);
            float4 k1v = *(const float4*)(pk + 4);
            *(float4*)&sk[tid][0] = k0v;
            *(float4*)&sk[tid][4] = k1v;
            ssum[tid] = k0v.x + k0v.y + k0v.z + k0v.w +
                        k1v.x + k1v.y + k1v.z + k1v.w;
            *(float4*)&sv[tid][0] = *(const float4*)(pv);
            *(float4*)&sv[tid][4] = *(const float4*)(pv + 4);
        }
        __syncthreads();

        const int jend = (kb == qb) ? (tid + 1) : 128;
        for (int j = 0; j < jend; j++) {
            float4 ka  = *(const float4*)&sk[j][0];
            float4 kb4 = *(const float4*)&sk[j][4];
            float d0 = qr[0] * ka.x;
            d0 = fmaf(qr[1], ka.y, d0);  d0 = fmaf(qr[2], ka.z, d0);
            d0 = fmaf(qr[3], ka.w, d0);  d0 = fmaf(qr[4], kb4.x, d0);
            d0 = fmaf(qr[5], kb4.y, d0); d0 = fmaf(qr[6], kb4.z, d0);
            d0 = fmaf(qr[7], kb4.w, d0);
            float p = __expf(2.f * d0 - sq - ssum[j]);
            l += p;
            float4 va = *(const float4*)&sv[j][0];
            float4 vb = *(const float4*)&sv[j][4];
            acc[0] = fmaf(p, va.x, acc[0]); acc[1] = fmaf(p, va.y, acc[1]);
            acc[2] = fmaf(p, va.z, acc[2]); acc[3] = fmaf(p, va.w, acc[3]);
            acc[4] = fmaf(p, vb.x, acc[4]); acc[5] = fmaf(p, vb.y, acc[5]);
            acc[6] = fmaf(p, vb.z, acc[6]); acc[7] = fmaf(p, vb.w, acc[7]);
        }
        __syncthreads();
    }

    const float inv = 1.f / l;
    #pragma unroll
    for (int d = 0; d < 8; d++) {
        const float a  = e0[c0 + d];
        const float bd = e1[c0 + d] - a;
        g_ao[(size_t)q0 * HB + c0 + d] = fmaf(bd, acc[d] * inv, a);
    }
}

// ---------------------------------------------------------------------------
extern "C" void kernel_launch(void* const* d_in, const int* in_sizes, int n_in,
                              void* d_out, int out_size)
{
    const float* hs = (const float*)d_in[0];
    const float* Wq = (const float*)d_in[1];
    const float* Wk = (const float*)d_in[2];
    const float* Wv = (const float*)d_in[3];
    const float* Wo = (const float*)d_in[4];
    const float* Wg = (const float*)d_in[5];
    const float* e0 = (const float*)d_in[6];
    const float* e1 = (const float*)d_in[7];
    float* out = (float*)d_out;

    float *pq, *pk, *pv, *pao, *pO;
    __nv_bfloat16 *ahi, *alo, *bgh, *bgl, *bqh, *bql, *boh, *bol, *aoh, *aol;
    cudaGetSymbolAddress((void**)&pq,  g_pq);
    cudaGetSymbolAddress((void**)&pk,  g_pk);
    cudaGetSymbolAddress((void**)&pv,  g_pv);
    cudaGetSymbolAddress((void**)&pao, g_ao);
    cudaGetSymbolAddress((void**)&pO,  g_O);
    cudaGetSymbolAddress((void**)&ahi, g_ahi);
    cudaGetSymbolAddress((void**)&alo, g_alo);
    cudaGetSymbolAddress((void**)&bgh, g_bg_hi);
    cudaGetSymbolAddress((void**)&bgl, g_bg_lo);
    cudaGetSymbolAddress((void**)&bqh, g_bqkv_hi);
    cudaGetSymbolAddress((void**)&bql, g_bqkv_lo);
    cudaGetSymbolAddress((void**)&boh, g_bo_hi);
    cudaGetSymbolAddress((void**)&bol, g_bo_lo);
    cudaGetSymbolAddress((void**)&aoh, g_aoh);
    cudaGetSymbolAddress((void**)&aol, g_aol);

    static int smem_set = 0;
    if (!smem_set) {
        cudaFuncSetAttribute(mma_gemm<0>, cudaFuncAttributeMaxDynamicSharedMemorySize, GSMEM);
        cudaFuncSetAttribute(mma_gemm<1>, cudaFuncAttributeMaxDynamicSharedMemorySize, GSMEM);
        cudaFuncSetAttribute(mma_gemm<2>, cudaFuncAttributeMaxDynamicSharedMemorySize, GSMEM);
        smem_set = 1;
    }

    // 1) conversions
    conv_split<<<4096, 256>>>(hs, ahi, alo, S_LEN * D_MODEL);
    conv_split_T<<<dim3(8, 64),  dim3(32, 8)>>>(Wq, bqh,            bql,            D_MODEL, HB);
    conv_split_T<<<dim3(8, 64),  dim3(32, 8)>>>(Wk, bqh + 256*2048, bql + 256*2048, D_MODEL, HB);
    conv_split_T<<<dim3(8, 64),  dim3(32, 8)>>>(Wv, bqh + 512*2048, bql + 512*2048, D_MODEL, HB);
    conv_split_T<<<dim3(64, 64), dim3(32, 8)>>>(Wg, bgh, bgl, D_MODEL, D_MODEL);
    conv_split_T<<<dim3(64, 8),  dim3(32, 8)>>>(Wo, boh, bol, HB, D_MODEL);

    // 2) pq/pk/pv = sigmoid(hs @ W{q,k,v})   [tensor cores]
    mma_gemm<1><<<dim3(6, 16), 256, GSMEM>>>(ahi, alo, bqh, bql, D_MODEL,
                                             pq, pk, pv, nullptr, 768);
    // 3) attention -> g_ao
    attn_kernel<<<dim3(16, NH), 128>>>(e0, e1);
    // 4) ao -> bf16 split
    conv_split<<<512, 256>>>(pao, aoh, aol, S_LEN * HB);
    // 5) O = ao @ Wo   [tensor cores]
    mma_gemm<0><<<dim3(16, 16), 256, GSMEM>>>(aoh, aol, boh, bol, HB,
                                              pO, nullptr, nullptr, nullptr, D_MODEL);
    // 6) out = sigmoid(hs @ Wg) * O   [tensor cores, fused epilogue]
    mma_gemm<2><<<dim3(16, 16), 256, GSMEM>>>(ahi, alo, bgh, bgl, D_MODEL,
                                              out, nullptr, nullptr, pO, D_MODEL);
}